// round 5
// baseline (speedup 1.0000x reference)
#include <cuda_runtime.h>
#include <math.h>

// ---------------------------------------------------------------------------
// YoloV1Loss — two kernels, NO device-scope fences/atomics.
// R4 post-mortem: last-block finalize's per-block __threadfence (gpu-scope ->
// CCTL.IVALL, L1D flush) cost ~17us. Kernel boundary gives ordering for free.
//  K1: R2's 42us main pass (smem 64B-chunk staging) + per-block csum.
//  K2: ONE 1024-thread block: scan counts, gated sum (csum for full blocks,
//      <=256-float partial for the single boundary block), noobj, write out.
// ---------------------------------------------------------------------------

#define RPB   256
#define MAXB  4096
#define NCLS  20
#define PAD   17
#define FTPB  1024   // finalize threads

__device__ int   g_counts[MAXB];
__device__ float g_noobj[MAXB];
__device__ float g_csum[MAXB];
__device__ float g_contrib[MAXB * RPB];

// ---------------- K1: main pass ----------------
__global__ void __launch_bounds__(RPB) yolo_main(const float* __restrict__ p,
                                                 const float* __restrict__ t,
                                                 int nrows) {
    __shared__ float ps[RPB * PAD];
    __shared__ float tsd[RPB * PAD];
    __shared__ int   wtot[RPB / 32];
    __shared__ float wredN[RPB / 32];
    __shared__ float wredC[RPB / 32];

    const int tid  = threadIdx.x;
    const int bid  = blockIdx.x;
    const int row0 = bid * RPB;
    const int lane = tid & 31;
    const int wid  = tid >> 5;

    // stage aligned 64B chunks covering floats [row*30 & ~7, +16)
    for (int j = tid; j < RPB * 4; j += RPB) {
        const int r    = j >> 2;
        const int part = j & 3;
        const int gr   = row0 + r;
        if (gr < nrows) {
            const int chunkf = (gr * 30) & ~7;
            const float4 pv = *(const float4*)(p + chunkf + part * 4);
            const float4 tv = *(const float4*)(t + chunkf + part * 4);
            const int si = r * PAD + part * 4;
            ps[si + 0] = pv.x; ps[si + 1] = pv.y;
            ps[si + 2] = pv.z; ps[si + 3] = pv.w;
            tsd[si + 0] = tv.x; tsd[si + 1] = tv.y;
            tsd[si + 2] = tv.z; tsd[si + 3] = tv.w;
        }
    }
    __syncthreads();

    const int  grow    = row0 + tid;
    const bool inrange = (grow < nrows);
    const int  off     = (grow * 30) & 7;
    const float* pr = ps  + tid * PAD + off;   // pr[c] == p[grow*30+c], c<10
    const float* tr = tsd + tid * PAD + off;

    const float conf = inrange ? tr[4] : -1.0f;
    const bool  cm   = (conf == 1.0f);

    // in-block inclusive rank of coord rows
    const unsigned bal = __ballot_sync(0xffffffffu, cm);
    unsigned le_mask;
    asm("mov.u32 %0, %%lanemask_le;" : "=r"(le_mask));
    const int inc = __popc(bal & le_mask);
    if (lane == 31) wtot[wid] = __popc(bal);
    __syncthreads();
    int woff = 0, ctot = 0;
#pragma unroll
    for (int i = 0; i < RPB / 32; i++) {
        const int c = wtot[i];
        if (i < wid) woff += c;
        ctot += c;
    }

    // noobj term
    float nv = 0.0f;
    if (inrange && conf == 0.0f) {
        const float d0 = pr[4] - tr[4];
        const float d1 = pr[9] - tr[9];
        nv = 0.5f * (d0 * d0 + d1 * d1);
    }

    // coord term (global gate resolved in K2)
    float cv = 0.0f;
    if (cm) {
        const float C = 1.0f / 7.0f;
        const float tb0 = tr[0] * tr[0], tb1 = tr[1] * tr[1];
        const float tb2 = tr[2] * tr[2], tb3 = tr[3] * tr[3];
        const float tax = tb0 * C - tb2, tay = tb1 * C - tb3;
        const float tbx = tax * C + tb2, tby = tay * C + tb3;
        const float at  = (tbx - tax) * (tby - tay);

        float iou0 = 0.0f, iou1 = 0.0f;
#pragma unroll
        for (int b = 0; b < 2; b++) {
            const float x = pr[b * 5 + 0], y = pr[b * 5 + 1];
            const float w = pr[b * 5 + 2], h = pr[b * 5 + 3];
            const float ax = x * C - w,  ay = y * C - h;
            const float bx = ax * C + w, by = ay * C + h;
            const float iw = fmaxf(fminf(bx, tbx) - fmaxf(ax, tax), 0.0f);
            const float ih = fmaxf(fminf(by, tby) - fmaxf(ay, tay), 0.0f);
            const float inter = iw * ih;
            const float ap = (bx - ax) * (by - ay);
            const float iou = inter / (ap + at - inter);
            if (b == 0) iou0 = iou; else iou1 = iou;
        }
        int idx;
        if (isnan(iou0))      idx = 0;   // numpy argmax: NaN wins, first occ.
        else if (isnan(iou1)) idx = 1;
        else                  idx = (iou1 > iou0) ? 1 : 0;

        const int ob = idx * 5;
        const float s0 = pr[ob + 0] - tr[0];
        const float s1 = pr[ob + 1] - tr[1];
        const float s2 = pr[ob + 2] - tr[2];
        const float s3 = pr[ob + 3] - tr[3];

        // lazy class gather: t[grow,10:30], first-strict argmax, paired p
        const float* tg = t + grow * 30 + 10;
        float best = -1.0f;
        int   oi   = 0;
#pragma unroll
        for (int j = 0; j < NCLS / 2; j++) {
            const float2 v = *(const float2*)(tg + 2 * j);
            if (v.x > best) { best = v.x; oi = 2 * j; }
            if (v.y > best) { best = v.y; oi = 2 * j + 1; }
        }
        const float clv = __ldg(p + grow * 30 + 10 + oi) - 1.0f;

        cv = 5.0f * (s0 * s0 + s1 * s1 + s2 * s2 + s3 * s3 + 2.0f * clv * clv);
        g_contrib[bid * RPB + (woff + inc - 1)] = cv;
    }

    // block reductions: noobj sum + coord sum
#pragma unroll
    for (int o = 16; o > 0; o >>= 1) {
        nv += __shfl_down_sync(0xffffffffu, nv, o);
        cv += __shfl_down_sync(0xffffffffu, cv, o);
    }
    if (lane == 0) { wredN[wid] = nv; wredC[wid] = cv; }
    __syncthreads();
    if (tid == 0) {
        float sn = 0.0f, sc = 0.0f;
#pragma unroll
        for (int i = 0; i < RPB / 32; i++) { sn += wredN[i]; sc += wredC[i]; }
        g_noobj[bid]  = sn;
        g_csum[bid]   = sc;
        g_counts[bid] = ctot;
    }
}

// ---------------- K2: single-block finalize ----------------
__global__ void __launch_bounds__(FTPB) yolo_finalize(float* __restrict__ out,
                                                      int nb) {
    const int tid  = threadIdx.x;
    const int lane = tid & 31;
    const int wid  = tid >> 5;
    const int CH   = (nb + FTPB - 1) / FTPB;   // counts per thread (4)
    const int i0   = tid * CH;

    // per-thread chunk sum of counts
    int lsum = 0;
#pragma unroll 4
    for (int k = 0; k < CH; k++) {
        const int i = i0 + k;
        if (i < nb) lsum += g_counts[i];
    }
    // warp inclusive scan
    int incs = lsum;
#pragma unroll
    for (int o = 1; o < 32; o <<= 1) {
        const int x = __shfl_up_sync(0xffffffffu, incs, o);
        if (lane >= o) incs += x;
    }
    const int ex = incs - lsum;

    // scan of 32 warp totals (warp 0)
    __shared__ int ws[FTPB / 32];
    __shared__ int wsx[FTPB / 32 + 1];
    __shared__ int s_bb, s_take;
    if (tid == 0) { s_bb = -1; s_take = 0; }
    if (lane == 31) ws[wid] = incs;
    __syncthreads();
    if (wid == 0) {
        int v = ws[lane];
#pragma unroll
        for (int o = 1; o < 32; o <<= 1) {
            const int x = __shfl_up_sync(0xffffffffu, v, o);
            if (lane >= o) v += x;
        }
        wsx[lane + 1] = v;
        if (lane == 0) wsx[0] = 0;
    }
    __syncthreads();
    const int total = wsx[FTPB / 32];
    const int half  = total >> 1;               // n_obj // 2

    // walk my chunk: csum for full blocks, locate the boundary block
    double acc = 0.0;
    int P = wsx[wid] + ex;
    for (int k = 0; k < CH; k++) {
        const int i = i0 + k;
        if (i < nb) {
            const int cnt  = g_counts[i];
            const int take = min(cnt, max(0, half - P));
            if (take == cnt)     acc += (double)g_csum[i];
            else if (take > 0) { s_bb = i; s_take = take; }
            acc += (double)g_noobj[i];
            P += cnt;
        }
    }
    __syncthreads();

    // partial boundary block (<=256 floats)
    if (s_bb >= 0) {
        const float* cb = g_contrib + s_bb * RPB;
        for (int i = tid; i < s_take; i += FTPB) acc += (double)cb[i];
    }

    // block reduce (double)
#pragma unroll
    for (int o = 16; o > 0; o >>= 1)
        acc += __shfl_down_sync(0xffffffffu, acc, o);
    __shared__ double sd[FTPB / 32];
    if (lane == 0) sd[wid] = acc;
    __syncthreads();
    if (tid == 0) {
        double s = 0.0;
#pragma unroll
        for (int i = 0; i < FTPB / 32; i++) s += sd[i];
        out[0] = (float)s;
    }
}

// ---------------------------------------------------------------------------
extern "C" void kernel_launch(void* const* d_in, const int* in_sizes, int n_in,
                              void* d_out, int out_size) {
    const float* p = (const float*)d_in[0];
    const float* t = (const float*)d_in[1];

    const int nrows   = in_sizes[0] / 30;
    const int nblocks = (nrows + RPB - 1) / RPB;

    yolo_main<<<nblocks, RPB>>>(p, t, nrows);
    yolo_finalize<<<1, FTPB>>>((float*)d_out, nblocks);
}

// round 6
// speedup vs baseline: 1.0486x; 1.0486x over previous
#include <cuda_runtime.h>
#include <math.h>

// ---------------------------------------------------------------------------
// YoloV1Loss — R6.
// K1: full-row contiguous staging (one DRAM phase, ~15 independent LDG.128
//     per thread, NO mid-compute gathers), per-block record = float4
//     (csum, noobj, count bitcast, unused).
// K2: one 1024-thread block; loads each record ONCE into registers (MLP=4),
//     scans counts, gated sum + <=256-float boundary partial, writes scalar.
// ---------------------------------------------------------------------------

#define RPB   256
#define MAXB  4096
#define NCLS  20
#define FTPB  1024

__device__ float4 g_meta[MAXB];            // (csum, noobj, count, 0)
__device__ float  g_contrib[MAXB * RPB];   // rank-compacted per block

// ---------------- K1: main pass ----------------
__global__ void __launch_bounds__(RPB) yolo_main(const float* __restrict__ p,
                                                 const float* __restrict__ t,
                                                 int nrows) {
    extern __shared__ float smem[];
    float* ps  = smem;                 // RPB*30 floats
    float* tsd = smem + RPB * 30;      // RPB*30 floats
    __shared__ int   wtot[RPB / 32];
    __shared__ float wredN[RPB / 32];
    __shared__ float wredC[RPB / 32];

    const int tid  = threadIdx.x;
    const int bid  = blockIdx.x;
    const int row0 = bid * RPB;
    const int lane = tid & 31;
    const int wid  = tid >> 5;
    const int rows = min(RPB, nrows - row0);
    const int n4   = (rows * 30) >> 2;               // rows*30 divisible by 4
    const size_t base = (size_t)row0 * 30;

    // full-row contiguous staging: pure float4 stream, one DRAM phase
    {
        const float4* pg = (const float4*)(p + base);
        const float4* tg = (const float4*)(t + base);
        float4* p4 = (float4*)ps;
        float4* t4 = (float4*)tsd;
        for (int i = tid; i < n4; i += RPB) {
            p4[i] = pg[i];
            t4[i] = tg[i];
        }
        // rows*30 may leave a remainder of 2 floats (rows odd) — scalar tail
        for (int i = (n4 << 2) + tid; i < rows * 30; i += RPB) {
            ps[i]  = p[base + i];
            tsd[i] = t[base + i];
        }
    }
    __syncthreads();

    const bool inrange = (tid < rows);
    const float* pr = ps  + tid * 30;
    const float* tr = tsd + tid * 30;

    const float conf = inrange ? tr[4] : -1.0f;
    const bool  cm   = (conf == 1.0f);

    // in-block inclusive rank of coord rows
    const unsigned bal = __ballot_sync(0xffffffffu, cm);
    unsigned le_mask;
    asm("mov.u32 %0, %%lanemask_le;" : "=r"(le_mask));
    const int inc = __popc(bal & le_mask);
    if (lane == 31) wtot[wid] = __popc(bal);
    __syncthreads();
    int woff = 0, ctot = 0;
#pragma unroll
    for (int i = 0; i < RPB / 32; i++) {
        const int c = wtot[i];
        if (i < wid) woff += c;
        ctot += c;
    }

    // noobj term
    float nv = 0.0f;
    if (inrange && conf == 0.0f) {
        const float d0 = pr[4] - tr[4];
        const float d1 = pr[9] - tr[9];
        nv = 0.5f * (d0 * d0 + d1 * d1);
    }

    // coord term (global gate resolved in K2)
    float cv = 0.0f;
    if (cm) {
        const float C = 1.0f / 7.0f;
        const float tb0 = tr[0] * tr[0], tb1 = tr[1] * tr[1];
        const float tb2 = tr[2] * tr[2], tb3 = tr[3] * tr[3];
        const float tax = tb0 * C - tb2, tay = tb1 * C - tb3;
        const float tbx = tax * C + tb2, tby = tay * C + tb3;
        const float at  = (tbx - tax) * (tby - tay);

        float iou0 = 0.0f, iou1 = 0.0f;
#pragma unroll
        for (int b = 0; b < 2; b++) {
            const float x = pr[b * 5 + 0], y = pr[b * 5 + 1];
            const float w = pr[b * 5 + 2], h = pr[b * 5 + 3];
            const float ax = x * C - w,  ay = y * C - h;
            const float bx = ax * C + w, by = ay * C + h;
            const float iw = fmaxf(fminf(bx, tbx) - fmaxf(ax, tax), 0.0f);
            const float ih = fmaxf(fminf(by, tby) - fmaxf(ay, tay), 0.0f);
            const float inter = iw * ih;
            const float ap = (bx - ax) * (by - ay);
            const float iou = inter / (ap + at - inter);
            if (b == 0) iou0 = iou; else iou1 = iou;
        }
        int idx;
        if (isnan(iou0))      idx = 0;   // numpy argmax: NaN wins, first occ.
        else if (isnan(iou1)) idx = 1;
        else                  idx = (iou1 > iou0) ? 1 : 0;

        const int ob = idx * 5;
        const float s0 = pr[ob + 0] - tr[0];
        const float s1 = pr[ob + 1] - tr[1];
        const float s2 = pr[ob + 2] - tr[2];
        const float s3 = pr[ob + 3] - tr[3];

        // class argmax from smem (first strict max) with paired p-select
        float best = tr[10];
        float clp  = pr[10];
#pragma unroll
        for (int j = 1; j < NCLS; j++) {
            const float v = tr[10 + j];
            const bool  u = (v > best);
            best = u ? v : best;
            clp  = u ? pr[10 + j] : clp;
        }
        const float clv = clp - 1.0f;

        cv = 5.0f * (s0 * s0 + s1 * s1 + s2 * s2 + s3 * s3 + 2.0f * clv * clv);
        g_contrib[bid * RPB + (woff + inc - 1)] = cv;
    }

    // block reductions: noobj + coord sums
#pragma unroll
    for (int o = 16; o > 0; o >>= 1) {
        nv += __shfl_down_sync(0xffffffffu, nv, o);
        cv += __shfl_down_sync(0xffffffffu, cv, o);
    }
    if (lane == 0) { wredN[wid] = nv; wredC[wid] = cv; }
    __syncthreads();
    if (tid == 0) {
        float sn = 0.0f, sc = 0.0f;
#pragma unroll
        for (int i = 0; i < RPB / 32; i++) { sn += wredN[i]; sc += wredC[i]; }
        g_meta[bid] = make_float4(sc, sn, __int_as_float(ctot), 0.0f);
    }
}

// ---------------- K2: single-block finalize ----------------
__global__ void __launch_bounds__(FTPB) yolo_finalize(float* __restrict__ out,
                                                      int nb) {
    const int tid  = threadIdx.x;
    const int lane = tid & 31;
    const int wid  = tid >> 5;
    const int CH   = (nb + FTPB - 1) / FTPB;   // records per thread
    const int i0   = tid * CH;

    // load my records ONCE into registers (independent -> MLP)
    float cs[4], no[4];
    int   cnt[4];
    int lsum = 0;
#pragma unroll
    for (int k = 0; k < 4; k++) {
        cs[k] = 0.0f; no[k] = 0.0f; cnt[k] = 0;
        const int i = i0 + k;
        if (k < CH && i < nb) {
            const float4 m = g_meta[i];
            cs[k]  = m.x;
            no[k]  = m.y;
            cnt[k] = __float_as_int(m.z);
            lsum  += cnt[k];
        }
    }

    // warp inclusive scan of per-thread count sums
    int incs = lsum;
#pragma unroll
    for (int o = 1; o < 32; o <<= 1) {
        const int x = __shfl_up_sync(0xffffffffu, incs, o);
        if (lane >= o) incs += x;
    }
    const int ex = incs - lsum;

    __shared__ int ws[FTPB / 32];
    __shared__ int wsx[FTPB / 32 + 1];
    __shared__ int s_bb, s_take;
    if (tid == 0) { s_bb = -1; s_take = 0; }
    if (lane == 31) ws[wid] = incs;
    __syncthreads();
    if (wid == 0) {
        int v = ws[lane];
#pragma unroll
        for (int o = 1; o < 32; o <<= 1) {
            const int x = __shfl_up_sync(0xffffffffu, v, o);
            if (lane >= o) v += x;
        }
        wsx[lane + 1] = v;
        if (lane == 0) wsx[0] = 0;
    }
    __syncthreads();
    const int half = wsx[FTPB / 32] >> 1;       // n_obj // 2

    // gated sum from registers; locate single boundary block
    double acc = 0.0;
    int P = wsx[wid] + ex;
#pragma unroll
    for (int k = 0; k < 4; k++) {
        const int i = i0 + k;
        if (k < CH && i < nb) {
            const int take = min(cnt[k], max(0, half - P));
            if (take == cnt[k])  acc += (double)cs[k];
            else if (take > 0) { s_bb = i; s_take = take; }
            acc += (double)no[k];
            P += cnt[k];
        }
    }
    __syncthreads();

    // partial boundary block (<=256 floats)
    if (s_bb >= 0) {
        const float* cb = g_contrib + s_bb * RPB;
        for (int i = tid; i < s_take; i += FTPB) acc += (double)cb[i];
    }

    // block reduce (double)
#pragma unroll
    for (int o = 16; o > 0; o >>= 1)
        acc += __shfl_down_sync(0xffffffffu, acc, o);
    __shared__ double sd[FTPB / 32];
    if (lane == 0) sd[wid] = acc;
    __syncthreads();
    if (tid == 0) {
        double s = 0.0;
#pragma unroll
        for (int i = 0; i < FTPB / 32; i++) s += sd[i];
        out[0] = (float)s;
    }
}

// ---------------------------------------------------------------------------
extern "C" void kernel_launch(void* const* d_in, const int* in_sizes, int n_in,
                              void* d_out, int out_size) {
    const float* p = (const float*)d_in[0];
    const float* t = (const float*)d_in[1];

    const int nrows   = in_sizes[0] / 30;
    const int nblocks = (nrows + RPB - 1) / RPB;

    const int smem_bytes = 2 * RPB * 30 * (int)sizeof(float);  // 61440
    cudaFuncSetAttribute(yolo_main, cudaFuncAttributeMaxDynamicSharedMemorySize,
                         smem_bytes);

    yolo_main<<<nblocks, RPB, smem_bytes>>>(p, t, nrows);
    yolo_finalize<<<1, FTPB>>>((float*)d_out, nblocks);
}